// round 5
// baseline (speedup 1.0000x reference)
#include <cuda_runtime.h>
#include <math.h>

// Problem constants
#define NPTS   2048
#define NNODES 8192
#define NCMP   1024
#define NWORDS 256           // NNODES / 32
#define CAP    192           // candidates/row (T=2.2 -> mean ~114, sigma ~10.6)
#define THRESH 2.2f

// Scratch (__device__ globals). g_bits is w-major: g_bits[w][c].
__device__ unsigned int       g_bits[NWORDS * NCMP];      // 1 MB
__device__ unsigned long long g_cand[(size_t)NPTS * CAP]; // {val:hi32, idx:lo32}, descending; 3 MB
__device__ int                g_cnt[NPTS];                // count per row, -1 = overflow

// ---------------------------------------------------------------------------
// Kernel A: pack mask (int32 [N, C] row-major) into w-major bitsets.
// Warp task = (word w, 32-column group). Lane owns 1 column (scalar loads,
// 128B/warp coalesced). 8192 warp tasks -> 1024 blocks x 8 warps.
// ---------------------------------------------------------------------------
__global__ __launch_bounds__(256) void pack_bits_kernel(const int* __restrict__ mask) {
    int warp = threadIdx.x >> 5;
    int lane = threadIdx.x & 31;
    int task = blockIdx.x * 8 + warp;      // 0..8191
    int w    = task >> 5;                  // 0..255
    int cg   = task & 31;                  // 0..31
    int c    = cg * 32 + lane;
    int n0   = w * 32;

    unsigned b0 = 0;
    const int* base = mask + (size_t)n0 * NCMP + c;
    #pragma unroll
    for (int i = 0; i < 32; i++) {
        b0 |= (unsigned)(base[(size_t)i * NCMP] != 0) << i;
    }
    g_bits[(size_t)w * NCMP + c] = b0;     // coalesced 128B/warp
}

// ---------------------------------------------------------------------------
// Kernel B: per-row candidate selection. Hot loop: 8 elements per group via
// FMNMX-tree + one compare; warp-uniform __any_sync branch to the hit path
// (prefix-sum offsets, one shared atomic per warp-group). Final order is made
// deterministic by the (value, index) rank sort, so scatter order is free.
// ---------------------------------------------------------------------------
__global__ __launch_bounds__(256) void select_cands_kernel(const float* __restrict__ x) {
    __shared__ float s_val[CAP];
    __shared__ int   s_idx[CAP];
    __shared__ int   s_cnt;

    int p    = blockIdx.x;
    int tid  = threadIdx.x;
    int lane = tid & 31;
    if (tid == 0) s_cnt = 0;
    __syncthreads();

    const float4* row4 = (const float4*)(x + (size_t)p * NNODES);
    #pragma unroll
    for (int g = 0; g < NNODES / (256 * 8); g++) {       // 4 groups of 8 elems/thread
        int q0 = tid + 512 * g;                          // two coalesced float4 slots
        float4 a = row4[q0];
        float4 b = row4[q0 + 256];
        float m = fmaxf(fmaxf(fmaxf(a.x, a.y), fmaxf(a.z, a.w)),
                        fmaxf(fmaxf(b.x, b.y), fmaxf(b.z, b.w)));
        bool hit = m > THRESH;
        if (__any_sync(0xFFFFFFFFu, hit)) {              // warp-uniform branch
            int cnt = 0;
            if (hit) {
                cnt = (a.x > THRESH) + (a.y > THRESH) + (a.z > THRESH) + (a.w > THRESH)
                    + (b.x > THRESH) + (b.y > THRESH) + (b.z > THRESH) + (b.w > THRESH);
            }
            // inclusive warp prefix of cnt
            int incl = cnt;
            #pragma unroll
            for (int d = 1; d < 32; d <<= 1) {
                int t = __shfl_up_sync(0xFFFFFFFFu, incl, d);
                if (lane >= d) incl += t;
            }
            int tot = __shfl_sync(0xFFFFFFFFu, incl, 31);
            int base = 0;
            if (lane == 31) base = atomicAdd(&s_cnt, tot);
            base = __shfl_sync(0xFFFFFFFFu, base, 31);
            if (hit) {
                int pos = base + incl - cnt;             // exclusive offset
                int n0 = q0 * 4, n1 = (q0 + 256) * 4;
                if (a.x > THRESH) { if (pos < CAP) { s_val[pos] = a.x; s_idx[pos] = n0;     } pos++; }
                if (a.y > THRESH) { if (pos < CAP) { s_val[pos] = a.y; s_idx[pos] = n0 + 1; } pos++; }
                if (a.z > THRESH) { if (pos < CAP) { s_val[pos] = a.z; s_idx[pos] = n0 + 2; } pos++; }
                if (a.w > THRESH) { if (pos < CAP) { s_val[pos] = a.w; s_idx[pos] = n0 + 3; } pos++; }
                if (b.x > THRESH) { if (pos < CAP) { s_val[pos] = b.x; s_idx[pos] = n1;     } pos++; }
                if (b.y > THRESH) { if (pos < CAP) { s_val[pos] = b.y; s_idx[pos] = n1 + 1; } pos++; }
                if (b.z > THRESH) { if (pos < CAP) { s_val[pos] = b.z; s_idx[pos] = n1 + 2; } pos++; }
                if (b.w > THRESH) { if (pos < CAP) { s_val[pos] = b.w; s_idx[pos] = n1 + 3; } pos++; }
            }
        }
    }
    __syncthreads();

    int nc = s_cnt;
    if (nc > CAP) {                                      // overflow -> exact fallback in C
        if (tid == 0) g_cnt[p] = -1;
        return;
    }
    if (tid == 0) g_cnt[p] = nc;

    if (tid < nc) {
        float v  = s_val[tid];
        int   id = s_idx[tid];
        int rank = 0;
        for (int j = 0; j < nc; j++) {
            float vj = s_val[j];
            rank += (vj > v) || (vj == v && s_idx[j] < id);
        }
        g_cand[(size_t)p * CAP + rank] =
            ((unsigned long long)__float_as_uint(v) << 32) | (unsigned int)id;
    }
}

// ---------------------------------------------------------------------------
// Kernel C: masked column max, batched candidate probe (8 at a time via 4
// independent 16B warp-uniform loads). Block = 32 columns x 128 rows; bitset
// tile [w][cl] in shared (bank-clean, coalesced to load).
// ---------------------------------------------------------------------------
#define TC  32
#define TPR 128

__global__ __launch_bounds__(256) void masked_colmax_kernel(const float* __restrict__ x,
                                                            float* __restrict__ out) {
    __shared__ unsigned int s_bits[NWORDS * TC];         // 32 KB

    int c0 = blockIdx.x * TC;
    int p0 = blockIdx.y * TPR;

    for (int i = threadIdx.x; i < NWORDS * (TC / 4); i += 256) {
        int w  = i >> 3;
        int cq = (i & 7) * 4;
        *(uint4*)(s_bits + w * TC + cq) =
            *(const uint4*)(g_bits + (size_t)w * NCMP + c0 + cq);
    }
    __syncthreads();

    int cl = threadIdx.x & 31;
    int pr = threadIdx.x >> 5;

    for (int p = p0 + pr; p < p0 + TPR; p += 8) {
        int cnt = g_cnt[p];                              // warp-uniform
        float res = 0.0f;
        bool found = false;
        if (cnt >= 0) {
            const ulonglong2* cand2 = (const ulonglong2*)(g_cand + (size_t)p * CAP);
            #pragma unroll 1
            for (int base = 0; base < cnt && !found; base += 8) {
                int b2 = base >> 1;                      // 4 independent 16B loads
                ulonglong2 e0 = cand2[b2 + 0];
                ulonglong2 e1 = cand2[b2 + 1];
                ulonglong2 e2 = cand2[b2 + 2];
                ulonglong2 e3 = cand2[b2 + 3];
                #define HIT(e, j, hv, vv)                                         \
                    unsigned idx##j = (unsigned)(e);                              \
                    float vv = __uint_as_float((unsigned)((e) >> 32));            \
                    bool hv = (base + j < cnt) &&                                 \
                        ((s_bits[(idx##j >> 5) * TC + cl] >> (idx##j & 31u)) & 1u);
                HIT(e0.x, 0, h0, v0) HIT(e0.y, 1, h1, v1)
                HIT(e1.x, 2, h2, v2) HIT(e1.y, 3, h3, v3)
                HIT(e2.x, 4, h4, v4) HIT(e2.y, 5, h5, v5)
                HIT(e3.x, 6, h6, v6) HIT(e3.y, 7, h7, v7)
                #undef HIT
                // first hit (smallest j) wins: assign in descending j order
                if (h7) res = v7; if (h6) res = v6; if (h5) res = v5; if (h4) res = v4;
                if (h3) res = v3; if (h2) res = v2; if (h1) res = v1; if (h0) res = v0;
                found = h0 | h1 | h2 | h3 | h4 | h5 | h6 | h7;
            }
        }
        if (!found) {
            // Exact fallback (overflow rows / no candidate masked / empty col).
            float m = -INFINITY;
            const float* row = x + (size_t)p * NNODES;
            for (int w = 0; w < NWORDS; w++) {
                unsigned int b = s_bits[w * TC + cl];
                while (b) {
                    int bit = __ffs(b) - 1;
                    m = fmaxf(m, row[w * 32 + bit]);
                    b &= b - 1;
                }
            }
            res = (m == -INFINITY) ? 0.0f : m;           // empty column -> 0.0
        }
        out[(size_t)p * NCMP + (c0 + cl)] = res;
    }
}

// ---------------------------------------------------------------------------
extern "C" void kernel_launch(void* const* d_in, const int* in_sizes, int n_in,
                              void* d_out, int out_size) {
    const float* x;
    const int*   mask;
    if (in_sizes[0] == NPTS * NNODES) {    // metadata order: x, learned_edge_states
        x    = (const float*)d_in[0];
        mask = (const int*)d_in[1];
    } else {
        x    = (const float*)d_in[1];
        mask = (const int*)d_in[0];
    }
    float* out = (float*)d_out;

    pack_bits_kernel<<<1024, 256>>>(mask);
    select_cands_kernel<<<NPTS, 256>>>(x);
    masked_colmax_kernel<<<dim3(NCMP / TC, NPTS / TPR), 256>>>(x, out);
}

// round 6
// speedup vs baseline: 1.3670x; 1.3670x over previous
#include <cuda_runtime.h>
#include <math.h>

// Problem constants
#define NPTS   2048
#define NNODES 8192
#define NCMP   1024
#define NWORDS 256           // NNODES / 32
#define CAP    192           // candidates/row (T=2.2 -> mean ~114, sigma ~10.6)
#define THRESH 2.2f

// Scratch (__device__ globals). g_bits is w-major: g_bits[w][c].
__device__ unsigned int       g_bits[NWORDS * NCMP];      // 1 MB
__device__ unsigned long long g_cand[(size_t)NPTS * CAP]; // {val:hi32, idx:lo32}, descending; 3 MB
__device__ int                g_cnt[NPTS];                // count per row, -1 = overflow

// ---------------------------------------------------------------------------
// Kernel A: pack mask (int32 [N, C] row-major) into w-major bitsets.
// (R2 version — measured 9.4us.) Warp task = (word w, 64-column group); lane
// owns 2 columns via int2 loads, fully coalesced. 512 blocks x 8 warps.
// ---------------------------------------------------------------------------
__global__ __launch_bounds__(256) void pack_bits_kernel(const int* __restrict__ mask) {
    int warp = threadIdx.x >> 5;
    int lane = threadIdx.x & 31;
    int task = blockIdx.x * 8 + warp;      // 0..4095
    int w    = task >> 4;                  // 0..255
    int cg   = task & 15;                  // 0..15
    int c0   = cg * 64 + lane * 2;
    int n0   = w * 32;

    unsigned b0 = 0, b1 = 0;
    const int* base = mask + (size_t)n0 * NCMP + c0;
    #pragma unroll
    for (int i = 0; i < 32; i++) {
        int2 v = *(const int2*)(base + (size_t)i * NCMP);
        b0 |= (unsigned)(v.x != 0) << i;
        b1 |= (unsigned)(v.y != 0) << i;
    }
    uint2 o; o.x = b0; o.y = b1;
    *(uint2*)(g_bits + (size_t)w * NCMP + c0) = o;       // coalesced 256B/warp
}

// ---------------------------------------------------------------------------
// Kernel B: per-row candidate selection. All 8 float4 loads issued
// back-to-back into registers FIRST (MLP=8; no intrinsic between loads),
// then ballot-aggregated compaction (one shared atomic per warp per pass).
// Final order is made deterministic by the (value, index) rank sort.
// ---------------------------------------------------------------------------
__global__ __launch_bounds__(256) void select_cands_kernel(const float* __restrict__ x) {
    __shared__ float s_val[CAP];
    __shared__ int   s_idx[CAP];
    __shared__ int   s_cnt;

    int p    = blockIdx.x;
    int tid  = threadIdx.x;
    int lane = tid & 31;
    unsigned lt = (1u << lane) - 1u;
    if (tid == 0) s_cnt = 0;
    __syncthreads();

    // Load whole row: 8 independent float4 per thread, issued before any
    // warp intrinsic -> full memory-level parallelism.
    const float4* row4 = (const float4*)(x + (size_t)p * NNODES);
    float4 v[8];
    #pragma unroll
    for (int i = 0; i < 8; i++) v[i] = row4[tid + 256 * i];

    #pragma unroll
    for (int i = 0; i < 8; i++) {
        float4 a = v[i];
        int n = (tid + 256 * i) * 4;
        unsigned m0 = __ballot_sync(0xFFFFFFFFu, a.x > THRESH);
        unsigned m1 = __ballot_sync(0xFFFFFFFFu, a.y > THRESH);
        unsigned m2 = __ballot_sync(0xFFFFFFFFu, a.z > THRESH);
        unsigned m3 = __ballot_sync(0xFFFFFFFFu, a.w > THRESH);
        int tot = __popc(m0) + __popc(m1) + __popc(m2) + __popc(m3);
        int wbase = 0;
        if (lane == 0 && tot) wbase = atomicAdd(&s_cnt, tot);
        wbase = __shfl_sync(0xFFFFFFFFu, wbase, 0);
        int off = wbase;
        if (a.x > THRESH) { int pos = off + __popc(m0 & lt); if (pos < CAP) { s_val[pos] = a.x; s_idx[pos] = n;     } }
        off += __popc(m0);
        if (a.y > THRESH) { int pos = off + __popc(m1 & lt); if (pos < CAP) { s_val[pos] = a.y; s_idx[pos] = n + 1; } }
        off += __popc(m1);
        if (a.z > THRESH) { int pos = off + __popc(m2 & lt); if (pos < CAP) { s_val[pos] = a.z; s_idx[pos] = n + 2; } }
        off += __popc(m2);
        if (a.w > THRESH) { int pos = off + __popc(m3 & lt); if (pos < CAP) { s_val[pos] = a.w; s_idx[pos] = n + 3; } }
    }
    __syncthreads();

    int nc = s_cnt;
    if (nc > CAP) {                                      // overflow -> exact fallback in C
        if (tid == 0) g_cnt[p] = -1;
        return;
    }
    if (tid == 0) g_cnt[p] = nc;

    if (tid < nc) {
        float fv = s_val[tid];
        int   id = s_idx[tid];
        int rank = 0;
        for (int j = 0; j < nc; j++) {
            float vj = s_val[j];
            rank += (vj > fv) || (vj == fv && s_idx[j] < id);
        }
        g_cand[(size_t)p * CAP + rank] =
            ((unsigned long long)__float_as_uint(fv) << 32) | (unsigned int)id;
    }
}

// ---------------------------------------------------------------------------
// Kernel C: masked column max, batched candidate probe (8 at a time via 4
// independent 16B warp-uniform loads). Block = 32 columns x 128 rows; bitset
// tile [w][cl] in shared (bank-clean, coalesced to load).
// ---------------------------------------------------------------------------
#define TC  32
#define TPR 128

__global__ __launch_bounds__(256) void masked_colmax_kernel(const float* __restrict__ x,
                                                            float* __restrict__ out) {
    __shared__ unsigned int s_bits[NWORDS * TC];         // 32 KB

    int c0 = blockIdx.x * TC;
    int p0 = blockIdx.y * TPR;

    for (int i = threadIdx.x; i < NWORDS * (TC / 4); i += 256) {
        int w  = i >> 3;
        int cq = (i & 7) * 4;
        *(uint4*)(s_bits + w * TC + cq) =
            *(const uint4*)(g_bits + (size_t)w * NCMP + c0 + cq);
    }
    __syncthreads();

    int cl = threadIdx.x & 31;
    int pr = threadIdx.x >> 5;

    for (int p = p0 + pr; p < p0 + TPR; p += 8) {
        int cnt = g_cnt[p];                              // warp-uniform
        float res = 0.0f;
        bool found = false;
        if (cnt >= 0) {
            const ulonglong2* cand2 = (const ulonglong2*)(g_cand + (size_t)p * CAP);
            #pragma unroll 1
            for (int base = 0; base < cnt && !found; base += 8) {
                int b2 = base >> 1;                      // 4 independent 16B loads
                ulonglong2 e0 = cand2[b2 + 0];
                ulonglong2 e1 = cand2[b2 + 1];
                ulonglong2 e2 = cand2[b2 + 2];
                ulonglong2 e3 = cand2[b2 + 3];
                #define HIT(e, j, hv, vv)                                         \
                    unsigned idx##j = (unsigned)(e);                              \
                    float vv = __uint_as_float((unsigned)((e) >> 32));            \
                    bool hv = (base + j < cnt) &&                                 \
                        ((s_bits[(idx##j >> 5) * TC + cl] >> (idx##j & 31u)) & 1u);
                HIT(e0.x, 0, h0, v0) HIT(e0.y, 1, h1, v1)
                HIT(e1.x, 2, h2, v2) HIT(e1.y, 3, h3, v3)
                HIT(e2.x, 4, h4, v4) HIT(e2.y, 5, h5, v5)
                HIT(e3.x, 6, h6, v6) HIT(e3.y, 7, h7, v7)
                #undef HIT
                // first hit (smallest j) wins: assign in descending j order
                if (h7) res = v7; if (h6) res = v6; if (h5) res = v5; if (h4) res = v4;
                if (h3) res = v3; if (h2) res = v2; if (h1) res = v1; if (h0) res = v0;
                found = h0 | h1 | h2 | h3 | h4 | h5 | h6 | h7;
            }
        }
        if (!found) {
            // Exact fallback (overflow rows / no candidate masked / empty col).
            float m = -INFINITY;
            const float* row = x + (size_t)p * NNODES;
            for (int w = 0; w < NWORDS; w++) {
                unsigned int b = s_bits[w * TC + cl];
                while (b) {
                    int bit = __ffs(b) - 1;
                    m = fmaxf(m, row[w * 32 + bit]);
                    b &= b - 1;
                }
            }
            res = (m == -INFINITY) ? 0.0f : m;           // empty column -> 0.0
        }
        out[(size_t)p * NCMP + (c0 + cl)] = res;
    }
}

// ---------------------------------------------------------------------------
extern "C" void kernel_launch(void* const* d_in, const int* in_sizes, int n_in,
                              void* d_out, int out_size) {
    const float* x;
    const int*   mask;
    if (in_sizes[0] == NPTS * NNODES) {    // metadata order: x, learned_edge_states
        x    = (const float*)d_in[0];
        mask = (const int*)d_in[1];
    } else {
        x    = (const float*)d_in[1];
        mask = (const int*)d_in[0];
    }
    float* out = (float*)d_out;

    pack_bits_kernel<<<512, 256>>>(mask);
    select_cands_kernel<<<NPTS, 256>>>(x);
    masked_colmax_kernel<<<dim3(NCMP / TC, NPTS / TPR), 256>>>(x, out);
}

// round 7
// speedup vs baseline: 1.4971x; 1.0952x over previous
#include <cuda_runtime.h>
#include <math.h>

// Problem constants
#define NPTS   2048
#define NNODES 8192
#define NCMP   1024
#define NWORDS 256           // NNODES / 32
#define CAP    192           // candidates/row (T=2.2 -> mean ~114, sigma ~10.6)
#define THRESH 2.2f

// Scratch (__device__ globals). g_bits is w-major: g_bits[w][c].
__device__ unsigned int       g_bits[NWORDS * NCMP];      // 1 MB
__device__ unsigned long long g_cand[(size_t)NPTS * CAP]; // {val:hi32, idx:lo32}, descending; 3 MB
__device__ int                g_cnt[NPTS];                // count per row, -1 = overflow

// ---------------------------------------------------------------------------
// Kernel A: pack mask (int32 [N, C] row-major) into w-major bitsets.
// (R2 version — measured best ~9.1us.)
// ---------------------------------------------------------------------------
__global__ __launch_bounds__(256) void pack_bits_kernel(const int* __restrict__ mask) {
    int warp = threadIdx.x >> 5;
    int lane = threadIdx.x & 31;
    int task = blockIdx.x * 8 + warp;      // 0..4095
    int w    = task >> 4;                  // 0..255
    int cg   = task & 15;                  // 0..15
    int c0   = cg * 64 + lane * 2;
    int n0   = w * 32;

    unsigned b0 = 0, b1 = 0;
    const int* base = mask + (size_t)n0 * NCMP + c0;
    #pragma unroll
    for (int i = 0; i < 32; i++) {
        int2 v = *(const int2*)(base + (size_t)i * NCMP);
        b0 |= (unsigned)(v.x != 0) << i;
        b1 |= (unsigned)(v.y != 0) << i;
    }
    uint2 o; o.x = b0; o.y = b1;
    *(uint2*)(g_bits + (size_t)w * NCMP + c0) = o;       // coalesced 256B/warp
}

// ---------------------------------------------------------------------------
// Kernel B: per-row candidate selection (exact R4 form — measured best).
// Ballot-aggregated compaction, one shared atomic per warp per float4 pass;
// deterministic final order via (value, index) rank sort.
// ---------------------------------------------------------------------------
__global__ __launch_bounds__(256) void select_cands_kernel(const float* __restrict__ x) {
    __shared__ float s_val[CAP];
    __shared__ int   s_idx[CAP];
    __shared__ int   s_cnt;

    int p    = blockIdx.x;
    int tid  = threadIdx.x;
    int lane = tid & 31;
    unsigned lt = (1u << lane) - 1u;
    if (tid == 0) s_cnt = 0;
    __syncthreads();

    const float4* row4 = (const float4*)(x + (size_t)p * NNODES);
    #pragma unroll
    for (int i = 0; i < NNODES / (256 * 4); i++) {       // 8 passes
        int q = tid + 256 * i;
        float4 v = row4[q];
        int n = q * 4;
        unsigned m0 = __ballot_sync(0xFFFFFFFFu, v.x > THRESH);
        unsigned m1 = __ballot_sync(0xFFFFFFFFu, v.y > THRESH);
        unsigned m2 = __ballot_sync(0xFFFFFFFFu, v.z > THRESH);
        unsigned m3 = __ballot_sync(0xFFFFFFFFu, v.w > THRESH);
        int tot = __popc(m0) + __popc(m1) + __popc(m2) + __popc(m3);
        int wbase = 0;
        if (lane == 0 && tot) wbase = atomicAdd(&s_cnt, tot);
        wbase = __shfl_sync(0xFFFFFFFFu, wbase, 0);
        int off = wbase;
        if (v.x > THRESH) { int pos = off + __popc(m0 & lt); if (pos < CAP) { s_val[pos] = v.x; s_idx[pos] = n;     } }
        off += __popc(m0);
        if (v.y > THRESH) { int pos = off + __popc(m1 & lt); if (pos < CAP) { s_val[pos] = v.y; s_idx[pos] = n + 1; } }
        off += __popc(m1);
        if (v.z > THRESH) { int pos = off + __popc(m2 & lt); if (pos < CAP) { s_val[pos] = v.z; s_idx[pos] = n + 2; } }
        off += __popc(m2);
        if (v.w > THRESH) { int pos = off + __popc(m3 & lt); if (pos < CAP) { s_val[pos] = v.w; s_idx[pos] = n + 3; } }
    }
    __syncthreads();

    int nc = s_cnt;
    if (nc > CAP) {                                      // overflow -> exact fallback in C
        if (tid == 0) g_cnt[p] = -1;
        return;
    }
    if (tid == 0) g_cnt[p] = nc;

    if (tid < nc) {
        float fv = s_val[tid];
        int   id = s_idx[tid];
        int rank = 0;
        for (int j = 0; j < nc; j++) {
            float vj = s_val[j];
            rank += (vj > fv) || (vj == fv && s_idx[j] < id);
        }
        g_cand[(size_t)p * CAP + rank] =
            ((unsigned long long)__float_as_uint(fv) << 32) | (unsigned int)id;
    }
}

// ---------------------------------------------------------------------------
// Kernel C: masked column max. Per-block shared staging: row counts + first 8
// candidates per row loaded cooperatively (coalesced), so the common-case
// probe chain is pure LDS (29cyc) instead of serial L2 rounds (~234cyc).
// Deeper batches (P~12% of warp-rows) still read from L2.
// ---------------------------------------------------------------------------
#define TC  32
#define TPR 128

__global__ __launch_bounds__(256) void masked_colmax_kernel(const float* __restrict__ x,
                                                            float* __restrict__ out) {
    __shared__ unsigned int       s_bits[NWORDS * TC];   // 32 KB
    __shared__ unsigned long long s_c8[TPR * 8];         // 8 KB: first 8 cands/row
    __shared__ int                s_rcnt[TPR];           // 512 B

    int c0 = blockIdx.x * TC;
    int p0 = blockIdx.y * TPR;

    for (int i = threadIdx.x; i < NWORDS * (TC / 4); i += 256) {
        int w  = i >> 3;
        int cq = (i & 7) * 4;
        *(uint4*)(s_bits + w * TC + cq) =
            *(const uint4*)(g_bits + (size_t)w * NCMP + c0 + cq);
    }
    if (threadIdx.x < TPR) s_rcnt[threadIdx.x] = g_cnt[p0 + threadIdx.x];
    #pragma unroll
    for (int k = 0; k < 4; k++) {
        int idx  = threadIdx.x + 256 * k;                // 0..1023
        int r    = idx >> 3;
        int slot = idx & 7;
        s_c8[idx] = g_cand[(size_t)(p0 + r) * CAP + slot];  // 64B/row, coalesced per warp
    }
    __syncthreads();

    int cl = threadIdx.x & 31;
    int pr = threadIdx.x >> 5;

    for (int r = pr; r < TPR; r += 8) {
        int p   = p0 + r;
        int cnt = s_rcnt[r];                             // LDS broadcast
        float res = 0.0f;
        bool found = false;
        if (cnt >= 0) {
            // Batch 1 (slots 0..7) from shared.
            const unsigned long long* c8 = s_c8 + r * 8;
            #define PROBE1(j)                                                     \
                unsigned long long e##j = c8[j];                                  \
                unsigned idx##j = (unsigned)e##j & (NNODES - 1);                  \
                float v##j = __uint_as_float((unsigned)(e##j >> 32));             \
                bool h##j = (j < cnt) &&                                          \
                    ((s_bits[(idx##j >> 5) * TC + cl] >> (idx##j & 31u)) & 1u);
            PROBE1(0) PROBE1(1) PROBE1(2) PROBE1(3)
            PROBE1(4) PROBE1(5) PROBE1(6) PROBE1(7)
            #undef PROBE1
            if (h7) res = v7; if (h6) res = v6; if (h5) res = v5; if (h4) res = v4;
            if (h3) res = v3; if (h2) res = v2; if (h1) res = v1; if (h0) res = v0;
            found = h0 | h1 | h2 | h3 | h4 | h5 | h6 | h7;

            // Deeper batches from global (rare).
            const ulonglong2* cand2 = (const ulonglong2*)(g_cand + (size_t)p * CAP);
            #pragma unroll 1
            for (int base = 8; base < cnt && !found; base += 8) {
                int b2 = base >> 1;
                ulonglong2 e0 = cand2[b2 + 0];
                ulonglong2 e1 = cand2[b2 + 1];
                ulonglong2 e2 = cand2[b2 + 2];
                ulonglong2 e3 = cand2[b2 + 3];
                #define HIT(e, j, hv, vv)                                         \
                    unsigned gidx##j = (unsigned)(e) & (NNODES - 1);              \
                    float vv = __uint_as_float((unsigned)((e) >> 32));            \
                    bool hv = (base + j < cnt) &&                                 \
                        ((s_bits[(gidx##j >> 5) * TC + cl] >> (gidx##j & 31u)) & 1u);
                HIT(e0.x, 0, g0, w0) HIT(e0.y, 1, g1, w1)
                HIT(e1.x, 2, g2, w2) HIT(e1.y, 3, g3, w3)
                HIT(e2.x, 4, g4, w4) HIT(e2.y, 5, g5, w5)
                HIT(e3.x, 6, g6, w6) HIT(e3.y, 7, g7, w7)
                #undef HIT
                if (g7) res = w7; if (g6) res = w6; if (g5) res = w5; if (g4) res = w4;
                if (g3) res = w3; if (g2) res = w2; if (g1) res = w1; if (g0) res = w0;
                found = g0 | g1 | g2 | g3 | g4 | g5 | g6 | g7;
            }
        }
        if (!found) {
            // Exact fallback (overflow rows / no candidate masked / empty col).
            float m = -INFINITY;
            const float* row = x + (size_t)p * NNODES;
            for (int w = 0; w < NWORDS; w++) {
                unsigned int b = s_bits[w * TC + cl];
                while (b) {
                    int bit = __ffs(b) - 1;
                    m = fmaxf(m, row[w * 32 + bit]);
                    b &= b - 1;
                }
            }
            res = (m == -INFINITY) ? 0.0f : m;           // empty column -> 0.0
        }
        out[(size_t)p * NCMP + (c0 + cl)] = res;
    }
}

// ---------------------------------------------------------------------------
extern "C" void kernel_launch(void* const* d_in, const int* in_sizes, int n_in,
                              void* d_out, int out_size) {
    const float* x;
    const int*   mask;
    if (in_sizes[0] == NPTS * NNODES) {    // metadata order: x, learned_edge_states
        x    = (const float*)d_in[0];
        mask = (const int*)d_in[1];
    } else {
        x    = (const float*)d_in[1];
        mask = (const int*)d_in[0];
    }
    float* out = (float*)d_out;

    // Order: B first (profiler capture window lands on the first launch ->
    // next profile shows select_cands). B reads only x, pack reads only mask;
    // stream order still serializes everything before C.
    select_cands_kernel<<<NPTS, 256>>>(x);
    pack_bits_kernel<<<512, 256>>>(mask);
    masked_colmax_kernel<<<dim3(NCMP / TC, NPTS / TPR), 256>>>(x, out);
}

// round 8
// speedup vs baseline: 1.6374x; 1.0937x over previous
#include <cuda_runtime.h>
#include <math.h>

// Problem constants
#define NPTS   2048
#define NNODES 8192
#define NCMP   1024
#define NWORDS 256           // NNODES / 32
#define CAP    192           // candidates/row (T=2.2 -> mean ~114, sigma ~10.6)
#define THRESH 2.2f

// Scratch (__device__ globals). g_bits is w-major: g_bits[w][c].
__device__ unsigned int       g_bits[NWORDS * NCMP];      // 1 MB
__device__ unsigned long long g_cand[(size_t)NPTS * CAP]; // {val:hi32, idx:lo32}, descending; 3 MB
__device__ int                g_cnt[NPTS];                // count per row, -1 = overflow

// ---------------------------------------------------------------------------
// Fused kernel A+B. Grid 2560: blocks with bid%5==4 are pack blocks (512,
// interleaved so pack's DRAM traffic overlaps B's issue-bound phase); the
// other 2048 are select blocks (one row each).
//
// Pack: mask (int32 [N,C] row-major) -> w-major bitsets (R2 form, best).
// Select: per-float4 max + compare; lane-PRIVATE hit path (atomicAdd + stores,
// no ballots/shuffles). s_val order is nondeterministic but the (value,index)
// rank sort makes the final candidate list deterministic.
// ---------------------------------------------------------------------------
__global__ __launch_bounds__(256) void ab_kernel(const float* __restrict__ x,
                                                 const int* __restrict__ mask) {
    int bid = blockIdx.x;
    if ((bid % 5) == 4) {
        // ---- pack block: 8 warp tasks ----
        int warp = threadIdx.x >> 5;
        int lane = threadIdx.x & 31;
        int task = (bid / 5) * 8 + warp;   // 0..4095
        int w    = task >> 4;              // 0..255
        int cg   = task & 15;              // 0..15
        int c0   = cg * 64 + lane * 2;
        int n0   = w * 32;

        unsigned b0 = 0, b1 = 0;
        const int* base = mask + (size_t)n0 * NCMP + c0;
        #pragma unroll
        for (int i = 0; i < 32; i++) {
            int2 v = *(const int2*)(base + (size_t)i * NCMP);
            b0 |= (unsigned)(v.x != 0) << i;
            b1 |= (unsigned)(v.y != 0) << i;
        }
        uint2 o; o.x = b0; o.y = b1;
        *(uint2*)(g_bits + (size_t)w * NCMP + c0) = o;   // coalesced 256B/warp
        return;
    }

    // ---- select block ----
    __shared__ float s_val[CAP];
    __shared__ int   s_idx[CAP];
    __shared__ int   s_cnt;

    int p   = bid - bid / 5;               // 0..2047
    int tid = threadIdx.x;
    if (tid == 0) s_cnt = 0;
    __syncthreads();

    const float4* row4 = (const float4*)(x + (size_t)p * NNODES);
    #pragma unroll
    for (int i = 0; i < NNODES / (256 * 4); i++) {       // 8 passes, loads hoisted
        int q = tid + 256 * i;
        float4 v = row4[q];
        float m = fmaxf(fmaxf(v.x, v.y), fmaxf(v.z, v.w));
        if (m > THRESH) {                                // ~1.7 lanes/warp-pass
            int n = q * 4;
            int cnt = (v.x > THRESH) + (v.y > THRESH) + (v.z > THRESH) + (v.w > THRESH);
            int pos = atomicAdd(&s_cnt, cnt);
            if (v.x > THRESH) { if (pos < CAP) { s_val[pos] = v.x; s_idx[pos] = n;     } pos++; }
            if (v.y > THRESH) { if (pos < CAP) { s_val[pos] = v.y; s_idx[pos] = n + 1; } pos++; }
            if (v.z > THRESH) { if (pos < CAP) { s_val[pos] = v.z; s_idx[pos] = n + 2; } pos++; }
            if (v.w > THRESH) { if (pos < CAP) { s_val[pos] = v.w; s_idx[pos] = n + 3; } pos++; }
        }
    }
    __syncthreads();

    int nc = s_cnt;
    if (nc > CAP) {                                      // overflow -> exact fallback in C
        if (tid == 0) g_cnt[p] = -1;
        return;
    }
    if (tid == 0) g_cnt[p] = nc;

    if (tid < nc) {
        float fv = s_val[tid];
        int   id = s_idx[tid];
        int rank = 0;
        for (int j = 0; j < nc; j++) {
            float vj = s_val[j];
            rank += (vj > fv) || (vj == fv && s_idx[j] < id);
        }
        g_cand[(size_t)p * CAP + rank] =
            ((unsigned long long)__float_as_uint(fv) << 32) | (unsigned int)id;
    }
}

// ---------------------------------------------------------------------------
// Kernel C: masked column max. Shared staging: row counts + first 16
// candidates per row (coalesced) -> probe chain is pure LDS in 99.95% of
// warp-rows. Block = 32 columns x 128 rows; bitset tile [w][cl] bank-clean.
// ---------------------------------------------------------------------------
#define TC  32
#define TPR 128
#define STAGE 16

__global__ __launch_bounds__(256) void masked_colmax_kernel(const float* __restrict__ x,
                                                            float* __restrict__ out) {
    __shared__ unsigned int       s_bits[NWORDS * TC];   // 32 KB
    __shared__ unsigned long long s_cs[TPR * STAGE];     // 16 KB
    __shared__ int                s_rcnt[TPR];           // 512 B

    int c0 = blockIdx.x * TC;
    int p0 = blockIdx.y * TPR;

    for (int i = threadIdx.x; i < NWORDS * (TC / 4); i += 256) {
        int w  = i >> 3;
        int cq = (i & 7) * 4;
        *(uint4*)(s_bits + w * TC + cq) =
            *(const uint4*)(g_bits + (size_t)w * NCMP + c0 + cq);
    }
    if (threadIdx.x < TPR) s_rcnt[threadIdx.x] = g_cnt[p0 + threadIdx.x];
    #pragma unroll
    for (int k = 0; k < (TPR * STAGE) / 256; k++) {      // 8 passes
        int idx  = threadIdx.x + 256 * k;                // 0..2047
        int r    = idx >> 4;
        int slot = idx & (STAGE - 1);
        s_cs[idx] = g_cand[(size_t)(p0 + r) * CAP + slot];  // 128B/row contiguous
    }
    __syncthreads();

    int cl = threadIdx.x & 31;
    int pr = threadIdx.x >> 5;

    for (int r = pr; r < TPR; r += 8) {
        int p   = p0 + r;
        int cnt = s_rcnt[r];                             // LDS broadcast
        float res = 0.0f;
        bool found = false;
        if (cnt >= 0) {
            const unsigned long long* cs = s_cs + r * STAGE;
            // Two batches of 8 from shared.
            #pragma unroll
            for (int base = 0; base < STAGE && !found; base += 8) {
                #define PROBE(j)                                                  \
                    unsigned long long e##j = cs[base + j];                       \
                    unsigned idx##j = (unsigned)e##j & (NNODES - 1);              \
                    float v##j = __uint_as_float((unsigned)(e##j >> 32));         \
                    bool h##j = (base + j < cnt) &&                               \
                        ((s_bits[(idx##j >> 5) * TC + cl] >> (idx##j & 31u)) & 1u);
                PROBE(0) PROBE(1) PROBE(2) PROBE(3)
                PROBE(4) PROBE(5) PROBE(6) PROBE(7)
                #undef PROBE
                if (h7) res = v7; if (h6) res = v6; if (h5) res = v5; if (h4) res = v4;
                if (h3) res = v3; if (h2) res = v2; if (h1) res = v1; if (h0) res = v0;
                found = h0 | h1 | h2 | h3 | h4 | h5 | h6 | h7;
            }
            // Deeper batches from global (p ~ 5e-4 per warp-row).
            const ulonglong2* cand2 = (const ulonglong2*)(g_cand + (size_t)p * CAP);
            #pragma unroll 1
            for (int base = STAGE; base < cnt && !found; base += 8) {
                int b2 = base >> 1;
                ulonglong2 e0 = cand2[b2 + 0];
                ulonglong2 e1 = cand2[b2 + 1];
                ulonglong2 e2 = cand2[b2 + 2];
                ulonglong2 e3 = cand2[b2 + 3];
                #define HIT(e, j, hv, vv)                                         \
                    unsigned gidx##j = (unsigned)(e) & (NNODES - 1);              \
                    float vv = __uint_as_float((unsigned)((e) >> 32));            \
                    bool hv = (base + j < cnt) &&                                 \
                        ((s_bits[(gidx##j >> 5) * TC + cl] >> (gidx##j & 31u)) & 1u);
                HIT(e0.x, 0, g0, w0) HIT(e0.y, 1, g1, w1)
                HIT(e1.x, 2, g2, w2) HIT(e1.y, 3, g3, w3)
                HIT(e2.x, 4, g4, w4) HIT(e2.y, 5, g5, w5)
                HIT(e3.x, 6, g6, w6) HIT(e3.y, 7, g7, w7)
                #undef HIT
                if (g7) res = w7; if (g6) res = w6; if (g5) res = w5; if (g4) res = w4;
                if (g3) res = w3; if (g2) res = w2; if (g1) res = w1; if (g0) res = w0;
                found = g0 | g1 | g2 | g3 | g4 | g5 | g6 | g7;
            }
        }
        if (!found) {
            // Exact fallback (overflow rows / no candidate masked / empty col).
            float m = -INFINITY;
            const float* row = x + (size_t)p * NNODES;
            for (int w = 0; w < NWORDS; w++) {
                unsigned int b = s_bits[w * TC + cl];
                while (b) {
                    int bit = __ffs(b) - 1;
                    m = fmaxf(m, row[w * 32 + bit]);
                    b &= b - 1;
                }
            }
            res = (m == -INFINITY) ? 0.0f : m;           // empty column -> 0.0
        }
        out[(size_t)p * NCMP + (c0 + cl)] = res;
    }
}

// ---------------------------------------------------------------------------
extern "C" void kernel_launch(void* const* d_in, const int* in_sizes, int n_in,
                              void* d_out, int out_size) {
    const float* x;
    const int*   mask;
    if (in_sizes[0] == NPTS * NNODES) {    // metadata order: x, learned_edge_states
        x    = (const float*)d_in[0];
        mask = (const int*)d_in[1];
    } else {
        x    = (const float*)d_in[1];
        mask = (const int*)d_in[0];
    }
    float* out = (float*)d_out;

    ab_kernel<<<2560, 256>>>(x, mask);     // pack + select fused/overlapped
    masked_colmax_kernel<<<dim3(NCMP / TC, NPTS / TPR), 256>>>(x, out);
}